// round 10
// baseline (speedup 1.0000x reference)
#include <cuda_runtime.h>
#include <cuda_fp16.h>
#include <math.h>
#include <stdint.h>

#define D      256
#define NS     4096
#define NTOT   8192
#define TILE   128
#define TBLK   64
#define NPAIRS (TBLK*(TBLK+1)/2)        // 2080
#define GRID_MMD 304

// ---------------- device state / scratch (zero-init at load) ----------------
__device__ float  g_sq[NTOT];
__device__ float  g_colsum[D];
__device__ double g_sumsq;
__device__ double g_acc;
__device__ float  g_cexp;
__device__ int    g_ticket;
__device__ int    g_done;
__device__ __align__(16) __half g_hi[NTOT * D];

// ---------------- helpers ----------------
__device__ __forceinline__ uint32_t smem_u32(const void* p) {
    uint32_t a;
    asm("{ .reg .u64 t; cvta.to.shared.u64 t, %1; cvt.u32.u64 %0, t; }" : "=r"(a) : "l"(p));
    return a;
}
__device__ __forceinline__ uint32_t swz(uint32_t off) {      // SW128 swizzle
    return off ^ ((off >> 3) & 0x70);
}
__device__ __forceinline__ void ldsm4(uint32_t* r, uint32_t addr) {
    asm volatile("ldmatrix.sync.aligned.m8n8.x4.shared.b16 {%0,%1,%2,%3}, [%4];"
                 : "=r"(r[0]), "=r"(r[1]), "=r"(r[2]), "=r"(r[3]) : "r"(addr));
}
__device__ __forceinline__ void mma16816(float* c, const uint32_t* a,
                                         uint32_t b0, uint32_t b1) {
    asm volatile(
        "mma.sync.aligned.m16n8k16.row.col.f32.f16.f16.f32 "
        "{%0,%1,%2,%3}, {%4,%5,%6,%7}, {%8,%9}, {%0,%1,%2,%3};"
        : "+f"(c[0]), "+f"(c[1]), "+f"(c[2]), "+f"(c[3])
        : "r"(a[0]), "r"(a[1]), "r"(a[2]), "r"(a[3]), "r"(b0), "r"(b1));
}
__device__ __forceinline__ void cpasync16(uint32_t dst, const void* src) {
    asm volatile("cp.async.cg.shared.global [%0], [%1], 16;" :: "r"(dst), "l"(src));
}
// ---- packed f32x2 ----
__device__ __forceinline__ uint64_t pk2(float a, float b) {
    uint64_t r; asm("mov.b64 %0, {%1, %2};" : "=l"(r) : "f"(a), "f"(b)); return r;
}
__device__ __forceinline__ void upk2(uint64_t v, float& a, float& b) {
    asm("mov.b64 {%0, %1}, %2;" : "=f"(a), "=f"(b) : "l"(v));
}
__device__ __forceinline__ uint64_t mul2(uint64_t a, uint64_t b) {
    uint64_t r; asm("mul.rn.f32x2 %0, %1, %2;" : "=l"(r) : "l"(a), "l"(b)); return r;
}
__device__ __forceinline__ uint64_t add2(uint64_t a, uint64_t b) {
    uint64_t r; asm("add.rn.f32x2 %0, %1, %2;" : "=l"(r) : "l"(a), "l"(b)); return r;
}
__device__ __forceinline__ uint64_t fma2(uint64_t a, uint64_t b, uint64_t c) {
    uint64_t r; asm("fma.rn.f32x2 %0, %1, %2, %3;" : "=l"(r) : "l"(a), "l"(b), "l"(c)); return r;
}
__device__ __forceinline__ float ex2f(float x) {
    float r; asm("ex2.approx.f32 %0, %1;" : "=f"(r) : "f"(x)); return r;
}

// pair index -> (bi, bj), bi <= bj
__device__ __forceinline__ void pairmap(int idx, int& bi, int& bj) {
    float tt = 2.f * TBLK + 1.f;
    bi = (int)((tt - sqrtf(tt * tt - 8.f * (float)idx)) * 0.5f);
    if (bi < 0) bi = 0;
    if (bi > TBLK - 1) bi = TBLK - 1;
    while (bi > 0 && bi * TBLK - bi * (bi - 1) / 2 > idx) --bi;
    while ((bi + 1) * TBLK - (bi + 1) * bi / 2 <= idx) ++bi;
    bj = bi + idx - (bi * TBLK - bi * (bi - 1) / 2);
}

// ---------------- fused stats + fp16 convert (single 8MB pass) ------------
// 256 blocks x 256 threads; block b owns rows [b*32, b*32+32)
#define SROWS 32
__global__ void k_stats(const float* __restrict__ src, const float* __restrict__ tgt) {
    __shared__ float colsm[8][256];
    __shared__ float wsum[8];
    int b = blockIdx.x, tid = threadIdx.x, lane = tid & 31, warp = tid >> 5;

    float colacc[8];
    #pragma unroll
    for (int e = 0; e < 8; ++e) colacc[e] = 0.f;

    float ssq_local = 0.f;
    #pragma unroll
    for (int rr = 0; rr < SROWS / 8; ++rr) {
        int r = warp + rr * 8;
        int i = b * SROWS + r;
        const float* row = (i < NS) ? src + (size_t)i * D : tgt + (size_t)(i - NS) * D;
        float4 v0 = ((const float4*)row)[lane * 2];
        float4 v1 = ((const float4*)row)[lane * 2 + 1];
        float vv[8] = {v0.x, v0.y, v0.z, v0.w, v1.x, v1.y, v1.z, v1.w};
        __half h[8];
        float s_ex = 0.f, s_hi = 0.f;
        #pragma unroll
        for (int e = 0; e < 8; ++e) {
            h[e] = __float2half(vv[e]);
            float hf = __half2float(h[e]);
            s_ex += vv[e] * vv[e];
            s_hi += hf * hf;
            colacc[e] += vv[e];
        }
        *(uint4*)&g_hi[(size_t)i * D + lane * 8] = *(uint4*)h;
        #pragma unroll
        for (int o = 16; o; o >>= 1) {
            s_ex += __shfl_xor_sync(0xffffffffu, s_ex, o);
            s_hi += __shfl_xor_sync(0xffffffffu, s_hi, o);
        }
        if (lane == 0) { g_sq[i] = s_hi; ssq_local += s_ex; }
    }
    #pragma unroll
    for (int e = 0; e < 8; ++e) colsm[warp][lane * 8 + e] = colacc[e];
    if (lane == 0) wsum[warp] = ssq_local;
    __syncthreads();

    float cs = 0.f;
    #pragma unroll
    for (int w = 0; w < 8; ++w) cs += colsm[w][tid];
    atomicAdd(&g_colsum[tid], cs);

    if (tid == 0) {
        double bs = 0.0;
        #pragma unroll
        for (int w = 0; w < 8; ++w) bs += (double)wsum[w];
        atomicAdd(&g_sumsq, bs);
    }
}

// ---------------- bandwidth (closed form, fp64, exact data) ----------------
__global__ void k_prep() {
    __shared__ double sh[256];
    float c = g_colsum[threadIdx.x];
    sh[threadIdx.x] = (double)c * (double)c;
    __syncthreads();
    for (int o = 128; o; o >>= 1) {
        if (threadIdx.x < o) sh[threadIdx.x] += sh[threadIdx.x + o];
        __syncthreads();
    }
    if (threadIdx.x == 0) {
        double n     = (double)NTOT;
        double sumL2 = 2.0 * n * g_sumsq - 2.0 * sh[0];
        double bw0   = sumL2 / (n * n - n) / 4.0;
        g_cexp = (float)(1.4426950408889634 / (bw0 * 16.0));  // a = 2^(-cexp*L2)
    }
}

// ---------------- main: persistent HMMA Gram tiles, 2-stage (R8 proven) --
// smem: [0..512) csn = -c*csq, [512..544) wred, [560..564) next-pair idx,
// buffers @1024: buf s in {0,1}: A @ 1024+s*32768, B @ +16384 (SW128)
#define SM_BUF   1024
#define SM_BYTES (1024 + 4 * 16384)

__global__ void __launch_bounds__(256, 2) k_mmd(float* __restrict__ out) {
    extern __shared__ char smem[];
    uint32_t sb = smem_u32(smem);
    int tid = threadIdx.x, wid = tid >> 5, lane = tid & 31;
    float* csn   = (float*)smem;
    float* wred  = (float*)(smem + 512);
    int*   sidx  = (int*)(smem + 560);

    // per-thread load mapping (4 x 16B per tile)
    int erow[4], eq[4];
    #pragma unroll
    for (int i = 0; i < 4; ++i) { int e = tid + i * 256; erow[i] = e >> 3; eq[i] = e & 7; }

    auto issue = [&](const __half* A, const __half* B, int c) {
        uint32_t ab = sb + SM_BUF + (c & 1) * 32768;
        uint32_t bb = ab + 16384;
        const char* As = (const char*)(A + c * 64);
        const char* Bs = (const char*)(B + c * 64);
        #pragma unroll
        for (int i = 0; i < 4; ++i) {
            uint32_t off = swz(erow[i] * 128 + eq[i] * 16);
            size_t go = (size_t)erow[i] * 512 + eq[i] * 16;
            cpasync16(ab + off, As + go);
            cpasync16(bb + off, Bs + go);
        }
        asm volatile("cp.async.commit_group;" ::: "memory");
    };

    // ---- warp tiling: 4 warps along M (32 each), 2 along N (64 each) ----
    int warp_m = wid & 3, warp_n = wid >> 2;
    int lane7 = lane & 7;
    int aRowOff = ((lane >> 3) & 1) * 8, aKoff = ((lane >> 4) & 1) * 8;
    int bNoff   = ((lane >> 4) & 1) * 8, bKoff = ((lane >> 3) & 1) * 8;
    uint32_t rowA[2], rowB[4];
    #pragma unroll
    for (int f = 0; f < 2; ++f)
        rowA[f] = (warp_m * 32 + f * 16 + aRowOff + lane7) * 128;
    #pragma unroll
    for (int q = 0; q < 4; ++q)
        rowB[q] = (warp_n * 64 + q * 16 + bNoff + lane7) * 128;
    int lr = lane >> 2, lc = (lane & 3) * 2;

    float ce = g_cexp;
    uint64_t twoc2 = pk2(2.f * ce, 2.f * ce);

    // ---- first ticket ----
    if (tid == 0) *sidx = atomicAdd(&g_ticket, 1);
    __syncthreads();
    int idx = *sidx;
    int bi = 0, bj = 0;
    const __half *A = g_hi, *B = g_hi;
    pairmap(idx, bi, bj);
    A = g_hi + (size_t)bi * TILE * D;
    B = g_hi + (size_t)bj * TILE * D;
    issue(A, B, 0);
    if (tid < 128) csn[tid] = -ce * g_sq[bj * TILE + tid];

    while (true) {
        float C[2][8][4];
        #pragma unroll
        for (int f = 0; f < 2; ++f)
            #pragma unroll
            for (int g = 0; g < 8; ++g)
                #pragma unroll
                for (int r = 0; r < 4; ++r) C[f][g][r] = 0.f;

        for (int c = 0; c < 4; ++c) {
            asm volatile("cp.async.wait_group 0;" ::: "memory");
            __syncthreads();
            if (c < 3) issue(A, B, c + 1);
            uint32_t ab = sb + SM_BUF + (c & 1) * 32768;
            uint32_t bb = ab + 16384;
            #pragma unroll
            for (int ks = 0; ks < 4; ++ks) {
                uint32_t kbA = (ks * 16 + aKoff) * 2;
                uint32_t kbB = (ks * 16 + bKoff) * 2;
                uint32_t aH[2][4], b[4][4];
                #pragma unroll
                for (int f = 0; f < 2; ++f) ldsm4(aH[f], ab + swz(rowA[f] + kbA));
                #pragma unroll
                for (int q = 0; q < 4; ++q) ldsm4(b[q], bb + swz(rowB[q] + kbB));
                #pragma unroll
                for (int f = 0; f < 2; ++f)
                    #pragma unroll
                    for (int q = 0; q < 4; ++q) {
                        mma16816(C[f][2*q],   aH[f], b[q][0], b[q][1]);
                        mma16816(C[f][2*q+1], aH[f], b[q][2], b[q][3]);
                    }
            }
        }

        // ---- grab next pair, start its loads before our epilogue ----
        if (tid == 0) *sidx = atomicAdd(&g_ticket, 1);
        __syncthreads();
        int nidx = *sidx;
        bool more = (nidx < NPAIRS);
        int nbi = 0, nbj = 0;
        const __half *An = A, *Bn = B;
        if (more) {
            pairmap(nidx, nbi, nbj);
            An = g_hi + (size_t)nbi * TILE * D;
            Bn = g_hi + (size_t)nbj * TILE * D;
            issue(An, Bn, 0);
        }

        // ---- epilogue: u = 2c*dot - c*rsq - c*csq; w = a+a^2+a^4+a^8+a^16
        uint64_t rs2[2][2];
        #pragma unroll
        for (int f = 0; f < 2; ++f)
            #pragma unroll
            for (int h = 0; h < 2; ++h) {
                float v = -ce * g_sq[bi * TILE + warp_m * 32 + f * 16 + h * 8 + lr];
                rs2[f][h] = pk2(v, v);
            }
        uint64_t cs2[8];
        #pragma unroll
        for (int g = 0; g < 8; ++g) {
            float2 cv = *(const float2*)&csn[warp_n * 64 + g * 8 + lc];
            cs2[g] = pk2(cv.x, cv.y);
        }

        uint64_t acc2 = pk2(0.f, 0.f);
        #pragma unroll
        for (int f = 0; f < 2; ++f) {
            #pragma unroll
            for (int g = 0; g < 8; ++g) {
                #pragma unroll
                for (int h = 0; h < 2; ++h) {
                    uint64_t s2 = add2(cs2[g], rs2[f][h]);
                    uint64_t u2 = fma2(pk2(C[f][g][2*h], C[f][g][2*h+1]), twoc2, s2);
                    float u0, u1;
                    upk2(u2, u0, u1);
                    uint64_t p  = pk2(ex2f(u0), ex2f(u1));
                    uint64_t m2 = mul2(p, p);
                    uint64_t m4 = mul2(m2, m2);
                    uint64_t m8 = mul2(m4, m4);
                    uint64_t t  = fma2(m8, m8, m8);   // a16 + a8
                    t = add2(t, m4);
                    t = add2(t, m2);
                    t = add2(t, p);
                    acc2 = add2(acc2, t);
                }
            }
        }
        float t0, t1;
        upk2(acc2, t0, t1);
        float tsum = t0 + t1;
        #pragma unroll
        for (int o = 16; o; o >>= 1) tsum += __shfl_xor_sync(0xffffffffu, tsum, o);
        if (lane == 0) wred[wid] = tsum;
        __syncthreads();
        if (tid == 0) {
            double bs = 0.0;
            #pragma unroll
            for (int w = 0; w < 8; ++w) bs += (double)wred[w];
            double wgt = (bi == bj) ? 1.0 : 2.0;
            double sgn = ((bi < 32) == (bj < 32)) ? 1.0 : -1.0;
            atomicAdd(&g_acc, bs * wgt * sgn);
        }
        if (!more) break;
        if (tid < 128) csn[tid] = -ce * g_sq[nbj * TILE + tid];
        bi = nbi; bj = nbj; A = An; B = Bn;
    }

    // ---- last-block finalize + state reset (replaces k_zero/k_final) ----
    __threadfence();
    __shared__ int slast;
    if (tid == 0) slast = (atomicAdd(&g_done, 1) == GRID_MMD - 1) ? 1 : 0;
    __syncthreads();
    if (slast) {
        if (tid < D) g_colsum[tid] = 0.f;
        if (tid == 0) {
            out[0] = (float)(g_acc / ((double)NS * (double)NS));
            g_acc = 0.0; g_sumsq = 0.0; g_ticket = 0; g_done = 0;
        }
    }
}

// ---------------- launch ----------------
extern "C" void kernel_launch(void* const* d_in, const int* in_sizes, int n_in,
                              void* d_out, int out_size) {
    const float* src = (const float*)d_in[0];
    const float* tgt = (const float*)d_in[1];
    float* out = (float*)d_out;

    cudaFuncSetAttribute(k_mmd, cudaFuncAttributeMaxDynamicSharedMemorySize, SM_BYTES);

    k_stats<<<NTOT / SROWS, 256>>>(src, tgt);
    k_prep <<<1, 256>>>();
    k_mmd  <<<GRID_MMD, 256, SM_BYTES>>>(out);
}

// round 12
// speedup vs baseline: 1.7552x; 1.7552x over previous
#include <cuda_runtime.h>
#include <cuda_fp16.h>
#include <math.h>
#include <stdint.h>

#define D      256
#define NS     4096
#define NTOT   8192
#define TILE   128
#define TBLK   64
#define NPAIRS (TBLK*(TBLK+1)/2)        // 2080

// ---------------- device state / scratch (zero-init at load) ----------------
__device__ float  g_sq[NTOT];
__device__ float  g_colsum[D];
__device__ double g_sumsq;
__device__ double g_acc;
__device__ float  g_cexp;
__device__ int    g_sdone;
__device__ __align__(16) __half g_hi[NTOT * D];

// ---------------- helpers ----------------
__device__ __forceinline__ uint32_t smem_u32(const void* p) {
    uint32_t a;
    asm("{ .reg .u64 t; cvta.to.shared.u64 t, %1; cvt.u32.u64 %0, t; }" : "=r"(a) : "l"(p));
    return a;
}
__device__ __forceinline__ uint32_t swz(uint32_t off) {      // SW128 swizzle
    return off ^ ((off >> 3) & 0x70);
}
__device__ __forceinline__ void ldsm4(uint32_t* r, uint32_t addr) {
    asm volatile("ldmatrix.sync.aligned.m8n8.x4.shared.b16 {%0,%1,%2,%3}, [%4];"
                 : "=r"(r[0]), "=r"(r[1]), "=r"(r[2]), "=r"(r[3]) : "r"(addr));
}
__device__ __forceinline__ void mma16816(float* c, const uint32_t* a,
                                         uint32_t b0, uint32_t b1) {
    asm volatile(
        "mma.sync.aligned.m16n8k16.row.col.f32.f16.f16.f32 "
        "{%0,%1,%2,%3}, {%4,%5,%6,%7}, {%8,%9}, {%0,%1,%2,%3};"
        : "+f"(c[0]), "+f"(c[1]), "+f"(c[2]), "+f"(c[3])
        : "r"(a[0]), "r"(a[1]), "r"(a[2]), "r"(a[3]), "r"(b0), "r"(b1));
}
__device__ __forceinline__ void cpasync16(uint32_t dst, const void* src) {
    asm volatile("cp.async.cg.shared.global [%0], [%1], 16;" :: "r"(dst), "l"(src));
}
// ---- packed f32x2 ----
__device__ __forceinline__ uint64_t pk2(float a, float b) {
    uint64_t r; asm("mov.b64 %0, {%1, %2};" : "=l"(r) : "f"(a), "f"(b)); return r;
}
__device__ __forceinline__ void upk2(uint64_t v, float& a, float& b) {
    asm("mov.b64 {%0, %1}, %2;" : "=f"(a), "=f"(b) : "l"(v));
}
__device__ __forceinline__ uint64_t mul2(uint64_t a, uint64_t b) {
    uint64_t r; asm("mul.rn.f32x2 %0, %1, %2;" : "=l"(r) : "l"(a), "l"(b)); return r;
}
__device__ __forceinline__ uint64_t add2(uint64_t a, uint64_t b) {
    uint64_t r; asm("add.rn.f32x2 %0, %1, %2;" : "=l"(r) : "l"(a), "l"(b)); return r;
}
__device__ __forceinline__ uint64_t fma2(uint64_t a, uint64_t b, uint64_t c) {
    uint64_t r; asm("fma.rn.f32x2 %0, %1, %2, %3;" : "=l"(r) : "l"(a), "l"(b), "l"(c)); return r;
}
__device__ __forceinline__ float ex2f(float x) {
    float r; asm("ex2.approx.f32 %0, %1;" : "=f"(r) : "f"(x)); return r;
}

// ---------------- fused stats + fp16 convert + bw0 (tail block) -----------
// 512 blocks x 256 threads; block b owns rows [b*16, b*16+16)
#define SROWS   16
#define SGRID   (NTOT / SROWS)          // 512
__global__ void k_stats(const float* __restrict__ src, const float* __restrict__ tgt) {
    __shared__ float  colsm[8][256];
    __shared__ float  wsum[8];
    __shared__ int    slast;
    __shared__ double shd[256];
    int b = blockIdx.x, tid = threadIdx.x, lane = tid & 31, warp = tid >> 5;

    float colacc[8];
    #pragma unroll
    for (int e = 0; e < 8; ++e) colacc[e] = 0.f;

    float ssq_local = 0.f;
    #pragma unroll
    for (int rr = 0; rr < SROWS / 8; ++rr) {
        int i = b * SROWS + warp + rr * 8;
        const float* row = (i < NS) ? src + (size_t)i * D : tgt + (size_t)(i - NS) * D;
        float4 v0 = ((const float4*)row)[lane * 2];
        float4 v1 = ((const float4*)row)[lane * 2 + 1];
        float vv[8] = {v0.x, v0.y, v0.z, v0.w, v1.x, v1.y, v1.z, v1.w};
        __half h[8];
        float s_ex = 0.f, s_hi = 0.f;
        #pragma unroll
        for (int e = 0; e < 8; ++e) {
            h[e] = __float2half(vv[e]);
            float hf = __half2float(h[e]);
            s_ex += vv[e] * vv[e];
            s_hi += hf * hf;
            colacc[e] += vv[e];
        }
        *(uint4*)&g_hi[(size_t)i * D + lane * 8] = *(uint4*)h;
        #pragma unroll
        for (int o = 16; o; o >>= 1) {
            s_ex += __shfl_xor_sync(0xffffffffu, s_ex, o);
            s_hi += __shfl_xor_sync(0xffffffffu, s_hi, o);
        }
        if (lane == 0) { g_sq[i] = s_hi; ssq_local += s_ex; }
    }
    #pragma unroll
    for (int e = 0; e < 8; ++e) colsm[warp][lane * 8 + e] = colacc[e];
    if (lane == 0) wsum[warp] = ssq_local;
    __syncthreads();

    float cs = 0.f;
    #pragma unroll
    for (int w = 0; w < 8; ++w) cs += colsm[w][tid];
    atomicAdd(&g_colsum[tid], cs);

    if (tid == 0) {
        double bs = 0.0;
        #pragma unroll
        for (int w = 0; w < 8; ++w) bs += (double)wsum[w];
        atomicAdd(&g_sumsq, bs);
        __threadfence();
        slast = (atomicAdd(&g_sdone, 1) == SGRID - 1) ? 1 : 0;
    }
    __syncthreads();

    // ---- tail: last block computes bw0 -> g_cexp (replaces k_prep) ----
    if (slast) {
        __threadfence();
        float c = g_colsum[tid];
        shd[tid] = (double)c * (double)c;
        __syncthreads();
        for (int o = 128; o; o >>= 1) {
            if (tid < o) shd[tid] += shd[tid + o];
            __syncthreads();
        }
        if (tid == 0) {
            double n     = (double)NTOT;
            double sumL2 = 2.0 * n * g_sumsq - 2.0 * shd[0];
            double bw0   = sumL2 / (n * n - n) / 4.0;
            g_cexp = (float)(1.4426950408889634 / (bw0 * 16.0));  // a = 2^(-cexp*L2)
            g_sdone = 0;
        }
    }
}

// ---------------- main: HMMA Gram tiles (round-6 code, measured 57.7us) ---
// smem: [0..512) csq(128f), [512..544) wred,
// buffers @1024: buf s in {0,1}: A @ 1024+s*32768, B @ +16384 (SW128)
#define SM_BUF   1024
#define SM_BYTES (1024 + 4 * 16384)

__global__ void __launch_bounds__(256, 2) k_mmd() {
    extern __shared__ char smem[];
    uint32_t sb = smem_u32(smem);
    int tid = threadIdx.x, wid = tid >> 5, lane = tid & 31;

    // ---- linear pair index -> (bi, bj), bi <= bj ----
    int idx = blockIdx.x;
    float tt = 2.f * TBLK + 1.f;
    int bi = (int)((tt - sqrtf(tt * tt - 8.f * (float)idx)) * 0.5f);
    if (bi < 0) bi = 0;
    if (bi > TBLK - 1) bi = TBLK - 1;
    while (bi > 0 && bi * TBLK - bi * (bi - 1) / 2 > idx) --bi;
    while ((bi + 1) * TBLK - (bi + 1) * bi / 2 <= idx) ++bi;
    int bj = bi + idx - (bi * TBLK - bi * (bi - 1) / 2);

    const __half* A = g_hi + (size_t)bi * TILE * D;
    const __half* B = g_hi + (size_t)bj * TILE * D;

    // per-thread load mapping (4 x 16B per tile)
    int erow[4], eq[4];
    #pragma unroll
    for (int i = 0; i < 4; ++i) { int e = tid + i * 256; erow[i] = e >> 3; eq[i] = e & 7; }

    auto issue = [&](int c) {
        uint32_t ab = sb + SM_BUF + (c & 1) * 32768;
        uint32_t bb = ab + 16384;
        const char* As = (const char*)(A + c * 64);
        const char* Bs = (const char*)(B + c * 64);
        #pragma unroll
        for (int i = 0; i < 4; ++i) {
            uint32_t off = swz(erow[i] * 128 + eq[i] * 16);
            size_t go = (size_t)erow[i] * 512 + eq[i] * 16;
            cpasync16(ab + off, As + go);
            cpasync16(bb + off, Bs + go);
        }
        asm volatile("cp.async.commit_group;" ::: "memory");
    };
    issue(0);

    if (tid < 128) ((float*)smem)[tid] = g_sq[bj * TILE + tid];

    // ---- warp tiling: 4 warps along M (32 each), 2 along N (64 each) ----
    int warp_m = wid & 3, warp_n = wid >> 2;
    int lane7 = lane & 7;
    int aRowOff = ((lane >> 3) & 1) * 8, aKoff = ((lane >> 4) & 1) * 8;
    int bNoff   = ((lane >> 4) & 1) * 8, bKoff = ((lane >> 3) & 1) * 8;

    uint32_t rowA[2], rowB[4];
    #pragma unroll
    for (int f = 0; f < 2; ++f)
        rowA[f] = (warp_m * 32 + f * 16 + aRowOff + lane7) * 128;
    #pragma unroll
    for (int q = 0; q < 4; ++q)
        rowB[q] = (warp_n * 64 + q * 16 + bNoff + lane7) * 128;

    float C[2][8][4];
    #pragma unroll
    for (int f = 0; f < 2; ++f)
        #pragma unroll
        for (int g = 0; g < 8; ++g)
            #pragma unroll
            for (int r = 0; r < 4; ++r) C[f][g][r] = 0.f;

    for (int c = 0; c < 4; ++c) {
        asm volatile("cp.async.wait_group 0;" ::: "memory");
        __syncthreads();
        if (c < 3) issue(c + 1);

        uint32_t ab = sb + SM_BUF + (c & 1) * 32768;
        uint32_t bb = ab + 16384;
        #pragma unroll
        for (int ks = 0; ks < 4; ++ks) {
            uint32_t kbA = (ks * 16 + aKoff) * 2;
            uint32_t kbB = (ks * 16 + bKoff) * 2;
            uint32_t aH[2][4], b[4][4];
            #pragma unroll
            for (int f = 0; f < 2; ++f) ldsm4(aH[f], ab + swz(rowA[f] + kbA));
            #pragma unroll
            for (int q = 0; q < 4; ++q) ldsm4(b[q], bb + swz(rowB[q] + kbB));
            #pragma unroll
            for (int f = 0; f < 2; ++f)
                #pragma unroll
                for (int q = 0; q < 4; ++q) {
                    mma16816(C[f][2*q],   aH[f], b[q][0], b[q][1]);
                    mma16816(C[f][2*q+1], aH[f], b[q][2], b[q][3]);
                }
        }
    }

    // ---- epilogue: u = 2c*dot - c*(rsq+csq); w = a+a^2+a^4+a^8+a^16 ------
    float ce   = g_cexp;
    float twoc = 2.f * ce;
    int lr = lane >> 2, lc = (lane & 3) * 2;

    float rs[2][2];                                   // -c * rsq
    #pragma unroll
    for (int f = 0; f < 2; ++f)
        #pragma unroll
        for (int h = 0; h < 2; ++h)
            rs[f][h] = -ce * g_sq[bi * TILE + warp_m * 32 + f * 16 + h * 8 + lr];

    float csn[16];                                    // -c * csq
    const float* csq = (const float*)smem;
    #pragma unroll
    for (int g = 0; g < 8; ++g) {
        csn[g * 2]     = -ce * csq[warp_n * 64 + g * 8 + lc];
        csn[g * 2 + 1] = -ce * csq[warp_n * 64 + g * 8 + lc + 1];
    }

    uint64_t acc2 = pk2(0.f, 0.f);
    #pragma unroll
    for (int f = 0; f < 2; ++f) {
        #pragma unroll
        for (int g = 0; g < 8; ++g) {
            #pragma unroll
            for (int h = 0; h < 2; ++h) {             // pair (col lc, lc+1)
                float u0 = fmaf(C[f][g][2*h],   twoc, rs[f][h] + csn[g*2]);
                float u1 = fmaf(C[f][g][2*h+1], twoc, rs[f][h] + csn[g*2+1]);
                uint64_t p  = pk2(ex2f(u0), ex2f(u1));
                uint64_t m2 = mul2(p, p);
                uint64_t m4 = mul2(m2, m2);
                uint64_t m8 = mul2(m4, m4);
                uint64_t t  = fma2(m8, m8, m8);       // a16 + a8
                t = add2(t, m4);
                t = add2(t, m2);
                t = add2(t, p);
                acc2 = add2(acc2, t);
            }
        }
    }
    float t0, t1;
    upk2(acc2, t0, t1);
    float tsum = t0 + t1;

    #pragma unroll
    for (int o = 16; o; o >>= 1) tsum += __shfl_xor_sync(0xffffffffu, tsum, o);
    if (lane == 0) ((float*)(smem + 512))[wid] = tsum;
    __syncthreads();

    if (tid == 0) {
        const float* wr = (const float*)(smem + 512);
        double bs = 0.0;
        #pragma unroll
        for (int w = 0; w < 8; ++w) bs += (double)wr[w];
        double wgt = (bi == bj) ? 1.0 : 2.0;
        double sgn = ((bi < 32) == (bj < 32)) ? 1.0 : -1.0;
        atomicAdd(&g_acc, bs * wgt * sgn);
    }
}

// ---------------- finalize + state reset (replaces k_zero/k_final) -------
__global__ void k_final(float* __restrict__ out) {
    int tid = threadIdx.x;
    if (tid < D) g_colsum[tid] = 0.f;
    if (tid == 0) {
        out[0] = (float)(g_acc / ((double)NS * (double)NS));
        g_acc = 0.0; g_sumsq = 0.0;
    }
}

// ---------------- launch ----------------
extern "C" void kernel_launch(void* const* d_in, const int* in_sizes, int n_in,
                              void* d_out, int out_size) {
    const float* src = (const float*)d_in[0];
    const float* tgt = (const float*)d_in[1];
    float* out = (float*)d_out;

    cudaFuncSetAttribute(k_mmd, cudaFuncAttributeMaxDynamicSharedMemorySize, SM_BYTES);

    k_stats<<<SGRID, 256>>>(src, tgt);
    k_mmd  <<<NPAIRS, 256, SM_BYTES>>>();
    k_final<<<1, 256>>>(out);
}

// round 13
// speedup vs baseline: 1.8168x; 1.0351x over previous
#include <cuda_runtime.h>
#include <cuda_fp16.h>
#include <math.h>
#include <stdint.h>

#define D      256
#define NS     4096
#define NTOT   8192
#define TILE   128
#define TBLK   64
#define NPAIRS (TBLK*(TBLK+1)/2)        // 2080

// ---------------- device state / scratch (zero-init at load) ----------------
__device__ float  g_sq[NTOT];
__device__ float  g_colsum[D];
__device__ double g_sumsq;
__device__ double g_acc;
__device__ float  g_cexp;
__device__ int    g_sdone;
__device__ __align__(16) __half g_hi[NTOT * D];

// ---------------- helpers ----------------
__device__ __forceinline__ uint32_t smem_u32(const void* p) {
    uint32_t a;
    asm("{ .reg .u64 t; cvta.to.shared.u64 t, %1; cvt.u32.u64 %0, t; }" : "=r"(a) : "l"(p));
    return a;
}
__device__ __forceinline__ uint32_t swz(uint32_t off) {      // SW128 swizzle
    return off ^ ((off >> 3) & 0x70);
}
__device__ __forceinline__ void ldsm4(uint32_t* r, uint32_t addr) {
    asm volatile("ldmatrix.sync.aligned.m8n8.x4.shared.b16 {%0,%1,%2,%3}, [%4];"
                 : "=r"(r[0]), "=r"(r[1]), "=r"(r[2]), "=r"(r[3]) : "r"(addr));
}
__device__ __forceinline__ void mma16816(float* c, const uint32_t* a,
                                         uint32_t b0, uint32_t b1) {
    asm volatile(
        "mma.sync.aligned.m16n8k16.row.col.f32.f16.f16.f32 "
        "{%0,%1,%2,%3}, {%4,%5,%6,%7}, {%8,%9}, {%0,%1,%2,%3};"
        : "+f"(c[0]), "+f"(c[1]), "+f"(c[2]), "+f"(c[3])
        : "r"(a[0]), "r"(a[1]), "r"(a[2]), "r"(a[3]), "r"(b0), "r"(b1));
}
__device__ __forceinline__ void cpasync16(uint32_t dst, const void* src) {
    asm volatile("cp.async.cg.shared.global [%0], [%1], 16;" :: "r"(dst), "l"(src));
}
// ---- packed f32x2 ----
__device__ __forceinline__ uint64_t pk2(float a, float b) {
    uint64_t r; asm("mov.b64 %0, {%1, %2};" : "=l"(r) : "f"(a), "f"(b)); return r;
}
__device__ __forceinline__ void upk2(uint64_t v, float& a, float& b) {
    asm("mov.b64 {%0, %1}, %2;" : "=f"(a), "=f"(b) : "l"(v));
}
__device__ __forceinline__ uint64_t mul2(uint64_t a, uint64_t b) {
    uint64_t r; asm("mul.rn.f32x2 %0, %1, %2;" : "=l"(r) : "l"(a), "l"(b)); return r;
}
__device__ __forceinline__ uint64_t add2(uint64_t a, uint64_t b) {
    uint64_t r; asm("add.rn.f32x2 %0, %1, %2;" : "=l"(r) : "l"(a), "l"(b)); return r;
}
__device__ __forceinline__ uint64_t fma2(uint64_t a, uint64_t b, uint64_t c) {
    uint64_t r; asm("fma.rn.f32x2 %0, %1, %2, %3;" : "=l"(r) : "l"(a), "l"(b), "l"(c)); return r;
}
__device__ __forceinline__ float ex2f(float x) {
    float r; asm("ex2.approx.f32 %0, %1;" : "=f"(r) : "f"(x)); return r;
}

// ---------------- fused stats + fp16 convert + bw0 (tail block) -----------
// 256 blocks x 256 threads; block b owns rows [b*32, b*32+32); warp owns 4.
#define SROWS   32
#define SGRID   (NTOT / SROWS)          // 256
__global__ void k_stats(const float* __restrict__ src, const float* __restrict__ tgt) {
    __shared__ float  colsm[8][256];
    __shared__ float  wsum[8];
    __shared__ int    slast;
    __shared__ double shd[256];
    int b = blockIdx.x, tid = threadIdx.x, lane = tid & 31, warp = tid >> 5;

    int i0 = b * SROWS + warp * 4;
    const float* rows[4];
    #pragma unroll
    for (int rr = 0; rr < 4; ++rr) {
        int i = i0 + rr;
        rows[rr] = (i < NS) ? src + (size_t)i * D : tgt + (size_t)(i - NS) * D;
    }
    // 8 independent LDG.128 up front (MLP 8)
    float4 va[4][2];
    #pragma unroll
    for (int rr = 0; rr < 4; ++rr) {
        va[rr][0] = ((const float4*)rows[rr])[lane * 2];
        va[rr][1] = ((const float4*)rows[rr])[lane * 2 + 1];
    }

    float colacc[8];
    #pragma unroll
    for (int e = 0; e < 8; ++e) colacc[e] = 0.f;

    float s_ex = 0.f;      // grand total only
    float s_hi[4];         // per-row rounded norms
    #pragma unroll
    for (int rr = 0; rr < 4; ++rr) {
        float vv[8] = {va[rr][0].x, va[rr][0].y, va[rr][0].z, va[rr][0].w,
                       va[rr][1].x, va[rr][1].y, va[rr][1].z, va[rr][1].w};
        __half h[8];
        float shi = 0.f;
        #pragma unroll
        for (int e = 0; e < 8; ++e) {
            h[e] = __float2half(vv[e]);
            float hf = __half2float(h[e]);
            s_ex += vv[e] * vv[e];
            shi  += hf * hf;
            colacc[e] += vv[e];
        }
        *(uint4*)&g_hi[(size_t)(i0 + rr) * D + lane * 8] = *(uint4*)h;
        s_hi[rr] = shi;
    }
    // 5 interleaved butterfly chains (4x s_hi + 1x s_ex)
    #pragma unroll
    for (int o = 16; o; o >>= 1) {
        #pragma unroll
        for (int rr = 0; rr < 4; ++rr)
            s_hi[rr] += __shfl_xor_sync(0xffffffffu, s_hi[rr], o);
        s_ex += __shfl_xor_sync(0xffffffffu, s_ex, o);
    }
    if (lane == 0) {
        #pragma unroll
        for (int rr = 0; rr < 4; ++rr) g_sq[i0 + rr] = s_hi[rr];
        wsum[warp] = s_ex;
    }
    #pragma unroll
    for (int e = 0; e < 8; ++e) colsm[warp][lane * 8 + e] = colacc[e];
    __syncthreads();

    float cs = 0.f;
    #pragma unroll
    for (int w = 0; w < 8; ++w) cs += colsm[w][tid];
    atomicAdd(&g_colsum[tid], cs);

    if (tid == 0) {
        double bs = 0.0;
        #pragma unroll
        for (int w = 0; w < 8; ++w) bs += (double)wsum[w];
        atomicAdd(&g_sumsq, bs);
        __threadfence();
        slast = (atomicAdd(&g_sdone, 1) == SGRID - 1) ? 1 : 0;
    }
    __syncthreads();

    // ---- tail: last block computes bw0 -> g_cexp (replaces k_prep) ----
    if (slast) {
        __threadfence();
        float c = g_colsum[tid];
        shd[tid] = (double)c * (double)c;
        __syncthreads();
        for (int o = 128; o; o >>= 1) {
            if (tid < o) shd[tid] += shd[tid + o];
            __syncthreads();
        }
        if (tid == 0) {
            double n     = (double)NTOT;
            double sumL2 = 2.0 * n * g_sumsq - 2.0 * shd[0];
            double bw0   = sumL2 / (n * n - n) / 4.0;
            g_cexp = (float)(1.4426950408889634 / (bw0 * 16.0));  // a = 2^(-cexp*L2)
            g_sdone = 0;
        }
    }
}

// ---------------- main: HMMA Gram tiles (R12 verbatim) --------------------
// smem: [0..512) csq(128f), [512..544) wred,
// buffers @1024: buf s in {0,1}: A @ 1024+s*32768, B @ +16384 (SW128)
#define SM_BUF   1024
#define SM_BYTES (1024 + 4 * 16384)

__global__ void __launch_bounds__(256, 2) k_mmd() {
    extern __shared__ char smem[];
    uint32_t sb = smem_u32(smem);
    int tid = threadIdx.x, wid = tid >> 5, lane = tid & 31;

    // ---- linear pair index -> (bi, bj), bi <= bj ----
    int idx = blockIdx.x;
    float tt = 2.f * TBLK + 1.f;
    int bi = (int)((tt - sqrtf(tt * tt - 8.f * (float)idx)) * 0.5f);
    if (bi < 0) bi = 0;
    if (bi > TBLK - 1) bi = TBLK - 1;
    while (bi > 0 && bi * TBLK - bi * (bi - 1) / 2 > idx) --bi;
    while ((bi + 1) * TBLK - (bi + 1) * bi / 2 <= idx) ++bi;
    int bj = bi + idx - (bi * TBLK - bi * (bi - 1) / 2);

    const __half* A = g_hi + (size_t)bi * TILE * D;
    const __half* B = g_hi + (size_t)bj * TILE * D;

    // per-thread load mapping (4 x 16B per tile)
    int erow[4], eq[4];
    #pragma unroll
    for (int i = 0; i < 4; ++i) { int e = tid + i * 256; erow[i] = e >> 3; eq[i] = e & 7; }

    auto issue = [&](int c) {
        uint32_t ab = sb + SM_BUF + (c & 1) * 32768;
        uint32_t bb = ab + 16384;
        const char* As = (const char*)(A + c * 64);
        const char* Bs = (const char*)(B + c * 64);
        #pragma unroll
        for (int i = 0; i < 4; ++i) {
            uint32_t off = swz(erow[i] * 128 + eq[i] * 16);
            size_t go = (size_t)erow[i] * 512 + eq[i] * 16;
            cpasync16(ab + off, As + go);
            cpasync16(bb + off, Bs + go);
        }
        asm volatile("cp.async.commit_group;" ::: "memory");
    };
    issue(0);

    if (tid < 128) ((float*)smem)[tid] = g_sq[bj * TILE + tid];

    // ---- warp tiling: 4 warps along M (32 each), 2 along N (64 each) ----
    int warp_m = wid & 3, warp_n = wid >> 2;
    int lane7 = lane & 7;
    int aRowOff = ((lane >> 3) & 1) * 8, aKoff = ((lane >> 4) & 1) * 8;
    int bNoff   = ((lane >> 4) & 1) * 8, bKoff = ((lane >> 3) & 1) * 8;

    uint32_t rowA[2], rowB[4];
    #pragma unroll
    for (int f = 0; f < 2; ++f)
        rowA[f] = (warp_m * 32 + f * 16 + aRowOff + lane7) * 128;
    #pragma unroll
    for (int q = 0; q < 4; ++q)
        rowB[q] = (warp_n * 64 + q * 16 + bNoff + lane7) * 128;

    float C[2][8][4];
    #pragma unroll
    for (int f = 0; f < 2; ++f)
        #pragma unroll
        for (int g = 0; g < 8; ++g)
            #pragma unroll
            for (int r = 0; r < 4; ++r) C[f][g][r] = 0.f;

    for (int c = 0; c < 4; ++c) {
        asm volatile("cp.async.wait_group 0;" ::: "memory");
        __syncthreads();
        if (c < 3) issue(c + 1);

        uint32_t ab = sb + SM_BUF + (c & 1) * 32768;
        uint32_t bb = ab + 16384;
        #pragma unroll
        for (int ks = 0; ks < 4; ++ks) {
            uint32_t kbA = (ks * 16 + aKoff) * 2;
            uint32_t kbB = (ks * 16 + bKoff) * 2;
            uint32_t aH[2][4], b[4][4];
            #pragma unroll
            for (int f = 0; f < 2; ++f) ldsm4(aH[f], ab + swz(rowA[f] + kbA));
            #pragma unroll
            for (int q = 0; q < 4; ++q) ldsm4(b[q], bb + swz(rowB[q] + kbB));
            #pragma unroll
            for (int f = 0; f < 2; ++f)
                #pragma unroll
                for (int q = 0; q < 4; ++q) {
                    mma16816(C[f][2*q],   aH[f], b[q][0], b[q][1]);
                    mma16816(C[f][2*q+1], aH[f], b[q][2], b[q][3]);
                }
        }
    }

    // ---- epilogue: u = 2c*dot - c*(rsq+csq); w = a+a^2+a^4+a^8+a^16 ------
    float ce   = g_cexp;
    float twoc = 2.f * ce;
    int lr = lane >> 2, lc = (lane & 3) * 2;

    float rs[2][2];                                   // -c * rsq
    #pragma unroll
    for (int f = 0; f < 2; ++f)
        #pragma unroll
        for (int h = 0; h < 2; ++h)
            rs[f][h] = -ce * g_sq[bi * TILE + warp_m * 32 + f * 16 + h * 8 + lr];

    float csn[16];                                    // -c * csq
    const float* csq = (const float*)smem;
    #pragma unroll
    for (int g = 0; g < 8; ++g) {
        csn[g * 2]     = -ce * csq[warp_n * 64 + g * 8 + lc];
        csn[g * 2 + 1] = -ce * csq[warp_n * 64 + g * 8 + lc + 1];
    }

    uint64_t acc2 = pk2(0.f, 0.f);
    #pragma unroll
    for (int f = 0; f < 2; ++f) {
        #pragma unroll
        for (int g = 0; g < 8; ++g) {
            #pragma unroll
            for (int h = 0; h < 2; ++h) {             // pair (col lc, lc+1)
                float u0 = fmaf(C[f][g][2*h],   twoc, rs[f][h] + csn[g*2]);
                float u1 = fmaf(C[f][g][2*h+1], twoc, rs[f][h] + csn[g*2+1]);
                uint64_t p  = pk2(ex2f(u0), ex2f(u1));
                uint64_t m2 = mul2(p, p);
                uint64_t m4 = mul2(m2, m2);
                uint64_t m8 = mul2(m4, m4);
                uint64_t t  = fma2(m8, m8, m8);       // a16 + a8
                t = add2(t, m4);
                t = add2(t, m2);
                t = add2(t, p);
                acc2 = add2(acc2, t);
            }
        }
    }
    float t0, t1;
    upk2(acc2, t0, t1);
    float tsum = t0 + t1;

    #pragma unroll
    for (int o = 16; o; o >>= 1) tsum += __shfl_xor_sync(0xffffffffu, tsum, o);
    if (lane == 0) ((float*)(smem + 512))[wid] = tsum;
    __syncthreads();

    if (tid == 0) {
        const float* wr = (const float*)(smem + 512);
        double bs = 0.0;
        #pragma unroll
        for (int w = 0; w < 8; ++w) bs += (double)wr[w];
        double wgt = (bi == bj) ? 1.0 : 2.0;
        double sgn = ((bi < 32) == (bj < 32)) ? 1.0 : -1.0;
        atomicAdd(&g_acc, bs * wgt * sgn);
    }
}

// ---------------- finalize + state reset ----------------------------------
__global__ void k_final(float* __restrict__ out) {
    int tid = threadIdx.x;
    if (tid < D) g_colsum[tid] = 0.f;
    if (tid == 0) {
        out[0] = (float)(g_acc / ((double)NS * (double)NS));
        g_acc = 0.0; g_sumsq = 0.0;
    }
}

// ---------------- launch ----------------
extern "C" void kernel_launch(void* const* d_in, const int* in_sizes, int n_in,
                              void* d_out, int out_size) {
    const float* src = (const float*)d_in[0];
    const float* tgt = (const float*)d_in[1];
    float* out = (float*)d_out;

    cudaFuncSetAttribute(k_mmd, cudaFuncAttributeMaxDynamicSharedMemorySize, SM_BYTES);

    k_stats<<<SGRID, 256>>>(src, tgt);
    k_mmd  <<<NPAIRS, 256, SM_BYTES>>>();
    k_final<<<1, 256>>>(out);
}